// round 2
// baseline (speedup 1.0000x reference)
#include <cuda_runtime.h>
#include <cuda_bf16.h>

#define N_NODES 50000
#define N_EDGES 600000
#define D 128
#define NCHUNK 49          // ceil(50000/1024)

// ---------------- scratch (static device globals; no allocation) -------------
__device__ int   g_is64;
__device__ int   g_cnt[N_NODES];
__device__ int   g_rowptr[N_NODES + 1];
__device__ int   g_cursor[N_NODES];
__device__ int   g_bsum[64];
__device__ int   g_srcidx[N_EDGES];
__device__ float g_agg[(size_t)N_NODES * D];
__device__ float g_h1 [(size_t)N_NODES * D];
__device__ float g_h2 [(size_t)N_NODES * D];

// Read edge_index element idx (idx in [0, 2*N_EDGES)) for either dtype.
__device__ __forceinline__ int edge_val(const void* ei, int idx) {
    if (g_is64) return (int)((const long long*)ei)[idx];
    return ((const int*)ei)[idx];
}

// ---------------- dtype detection -------------------------------------------
// int64 little-endian values < 2^31 have every odd int32 word == 0.
// For int32 edge data, odd words are real indices (P[all zero] ~ (1/5e4)^64).
__global__ void detect_kernel(const int* __restrict__ ei32) {
    if (threadIdx.x == 0) {
        int is64 = 1;
        for (int i = 0; i < 64; i++)
            if (ei32[2 * i + 1] != 0) { is64 = 0; break; }
        g_is64 = is64;
    }
}

// ---------------- CSR build --------------------------------------------------
__global__ void zero_cnt_kernel() {
    int i = blockIdx.x * blockDim.x + threadIdx.x;
    if (i < N_NODES) g_cnt[i] = 0;
}

__global__ void count_kernel(const void* __restrict__ ei) {
    int e = blockIdx.x * blockDim.x + threadIdx.x;
    if (e < N_EDGES) {
        int d = edge_val(ei, N_EDGES + e);   // dst row
        atomicAdd(&g_cnt[d], 1);
    }
}

__global__ void scan_partial_kernel() {
    __shared__ int s[1024];
    int i = blockIdx.x * 1024 + threadIdx.x;
    int v = (i < N_NODES) ? g_cnt[i] : 0;
    s[threadIdx.x] = v;
    __syncthreads();
    for (int off = 512; off > 0; off >>= 1) {
        if (threadIdx.x < off) s[threadIdx.x] += s[threadIdx.x + off];
        __syncthreads();
    }
    if (threadIdx.x == 0) g_bsum[blockIdx.x] = s[0];
}

__global__ void scan_bsums_kernel() {
    if (threadIdx.x == 0) {
        int acc = 0;
        for (int i = 0; i < NCHUNK; i++) {
            int v = g_bsum[i];
            g_bsum[i] = acc;
            acc += v;
        }
    }
}

__global__ void scan_write_kernel() {
    __shared__ int s[1024];
    int i = blockIdx.x * 1024 + threadIdx.x;
    int v = (i < N_NODES) ? g_cnt[i] : 0;
    s[threadIdx.x] = v;
    __syncthreads();
    // Hillis-Steele inclusive scan
    for (int off = 1; off < 1024; off <<= 1) {
        int t = (threadIdx.x >= off) ? s[threadIdx.x - off] : 0;
        __syncthreads();
        s[threadIdx.x] += t;
        __syncthreads();
    }
    if (i < N_NODES) {
        int excl = s[threadIdx.x] - v + g_bsum[blockIdx.x];
        g_rowptr[i] = excl;
        g_cursor[i] = excl;
        if (i == N_NODES - 1) g_rowptr[N_NODES] = excl + v;
    }
}

__global__ void fill_kernel(const void* __restrict__ ei) {
    int e = blockIdx.x * blockDim.x + threadIdx.x;
    if (e < N_EDGES) {
        int d = edge_val(ei, N_EDGES + e);
        int s = edge_val(ei, e);
        int pos = atomicAdd(&g_cursor[d], 1);
        g_srcidx[pos] = s;
    }
}

// ---------------- mean aggregation (warp per node, CSR gather) ---------------
__global__ void agg_kernel(const float* __restrict__ h) {
    int warp = (blockIdx.x * blockDim.x + threadIdx.x) >> 5;
    int lane = threadIdx.x & 31;
    if (warp >= N_NODES) return;
    int beg = g_rowptr[warp];
    int end = g_rowptr[warp + 1];
    float4 acc = make_float4(0.f, 0.f, 0.f, 0.f);
    for (int e = beg; e < end; e++) {
        int j = g_srcidx[e];                       // uniform across warp (broadcast)
        float4 v = *(const float4*)(h + (size_t)j * D + lane * 4);
        acc.x += v.x; acc.y += v.y; acc.z += v.z; acc.w += v.w;
    }
    float inv = 1.0f / fmaxf((float)(end - beg), 1.0f);
    acc.x *= inv; acc.y *= inv; acc.z *= inv; acc.w *= inv;
    *(float4*)(g_agg + (size_t)warp * D + lane * 4) = acc;
}

// ---------------- fused GEMM: out = relu(agg@Wl^T + h@Wr^T + bl) -------------
// C[M=50000, N=128] with K=256 (concat [agg|h] x [Wl|Wr]).
// CTA tile 128x128, thread tile 8x8, BK=16, 256 threads.
#define BM 128
#define BN 128
#define BK 16

__global__ __launch_bounds__(256, 2)
void gemm_kernel(const float* __restrict__ A,   // agg  [N_NODES, 128]
                 const float* __restrict__ H,   // h    [N_NODES, 128]
                 const float* __restrict__ Wl,  // [128, 128]
                 const float* __restrict__ Wr,  // [128, 128]
                 const float* __restrict__ bl,  // [128]
                 float* __restrict__ out) {
    __shared__ float As[BK][BM + 4];
    __shared__ float Bs[BK][BN + 4];

    int tid = threadIdx.x;
    int tx = tid & 15;        // n-dim thread coord (0..15)
    int ty = tid >> 4;        // m-dim thread coord (0..15)
    int m0 = blockIdx.x * BM;

    float c[8][8];
#pragma unroll
    for (int i = 0; i < 8; i++)
#pragma unroll
        for (int j = 0; j < 8; j++) c[i][j] = 0.f;

    for (int ch = 0; ch < 16; ch++) {
        const float* Aptr = (ch < 8) ? A : H;
        const float* Bptr = (ch < 8) ? Wl : Wr;
        int k0 = (ch & 7) * BK;

        // load A tile: 128 rows x 16 k  (2048 floats = 512 float4, 2 per thread)
#pragma unroll
        for (int q = 0; q < 2; q++) {
            int u  = tid * 2 + q;         // 0..511
            int m  = u >> 2;              // 0..127
            int kq = u & 3;               // which float4 within the 16-k row
            float4 v = make_float4(0.f, 0.f, 0.f, 0.f);
            int gm = m0 + m;
            if (gm < N_NODES)
                v = *(const float4*)(Aptr + (size_t)gm * D + k0 + kq * 4);
            As[kq * 4 + 0][m] = v.x;
            As[kq * 4 + 1][m] = v.y;
            As[kq * 4 + 2][m] = v.z;
            As[kq * 4 + 3][m] = v.w;
        }
        // load B tile: 128 n-rows x 16 k
#pragma unroll
        for (int q = 0; q < 2; q++) {
            int u  = tid * 2 + q;
            int n  = u >> 2;
            int kq = u & 3;
            float4 v = *(const float4*)(Bptr + n * D + k0 + kq * 4);
            Bs[kq * 4 + 0][n] = v.x;
            Bs[kq * 4 + 1][n] = v.y;
            Bs[kq * 4 + 2][n] = v.z;
            Bs[kq * 4 + 3][n] = v.w;
        }
        __syncthreads();

#pragma unroll
        for (int kk = 0; kk < BK; kk++) {
            float a[8], b[8];
            *(float4*)(a)     = *(const float4*)&As[kk][ty * 8];
            *(float4*)(a + 4) = *(const float4*)&As[kk][ty * 8 + 4];
            *(float4*)(b)     = *(const float4*)&Bs[kk][tx * 8];
            *(float4*)(b + 4) = *(const float4*)&Bs[kk][tx * 8 + 4];
#pragma unroll
            for (int i = 0; i < 8; i++)
#pragma unroll
                for (int j = 0; j < 8; j++)
                    c[i][j] += a[i] * b[j];
        }
        __syncthreads();
    }

    // epilogue: bias + relu + store
    float bias[8];
    *(float4*)(bias)     = *(const float4*)(bl + tx * 8);
    *(float4*)(bias + 4) = *(const float4*)(bl + tx * 8 + 4);

#pragma unroll
    for (int i = 0; i < 8; i++) {
        int gm = m0 + ty * 8 + i;
        if (gm >= N_NODES) break;
        float4 o0, o1;
        o0.x = fmaxf(c[i][0] + bias[0], 0.f);
        o0.y = fmaxf(c[i][1] + bias[1], 0.f);
        o0.z = fmaxf(c[i][2] + bias[2], 0.f);
        o0.w = fmaxf(c[i][3] + bias[3], 0.f);
        o1.x = fmaxf(c[i][4] + bias[4], 0.f);
        o1.y = fmaxf(c[i][5] + bias[5], 0.f);
        o1.z = fmaxf(c[i][6] + bias[6], 0.f);
        o1.w = fmaxf(c[i][7] + bias[7], 0.f);
        *(float4*)(out + (size_t)gm * D + tx * 8)     = o0;
        *(float4*)(out + (size_t)gm * D + tx * 8 + 4) = o1;
    }
}

// ---------------- launch ----------------------------------------------------
extern "C" void kernel_launch(void* const* d_in, const int* in_sizes, int n_in,
                              void* d_out, int out_size) {
    const float* x  = (const float*)d_in[0];
    const void*  ei = d_in[1];                  // int32 or int64, detected on device
    const float* Wl1 = (const float*)d_in[2];
    const float* bl1 = (const float*)d_in[3];
    const float* Wr1 = (const float*)d_in[4];
    const float* Wl2 = (const float*)d_in[5];
    const float* bl2 = (const float*)d_in[6];
    const float* Wr2 = (const float*)d_in[7];
    const float* Wl3 = (const float*)d_in[8];
    const float* bl3 = (const float*)d_in[9];
    const float* Wr3 = (const float*)d_in[10];
    float* out = (float*)d_out;

    float* agg; cudaGetSymbolAddress((void**)&agg, g_agg);
    float* h1;  cudaGetSymbolAddress((void**)&h1,  g_h1);
    float* h2;  cudaGetSymbolAddress((void**)&h2,  g_h2);

    // ---- detect edge dtype, build CSR (dst -> list of src) ----
    detect_kernel<<<1, 32>>>((const int*)ei);
    zero_cnt_kernel<<<(N_NODES + 255) / 256, 256>>>();
    count_kernel<<<(N_EDGES + 255) / 256, 256>>>(ei);
    scan_partial_kernel<<<NCHUNK, 1024>>>();
    scan_bsums_kernel<<<1, 32>>>();
    scan_write_kernel<<<NCHUNK, 1024>>>();
    fill_kernel<<<(N_EDGES + 255) / 256, 256>>>(ei);

    const int AGG_GRID  = (N_NODES * 32 + 255) / 256;      // warp per node
    const int GEMM_GRID = (N_NODES + BM - 1) / BM;         // 391

    // ---- layer 1: x -> h1 ----
    agg_kernel<<<AGG_GRID, 256>>>(x);
    gemm_kernel<<<GEMM_GRID, 256>>>(agg, x, Wl1, Wr1, bl1, h1);

    // ---- layer 2: h1 -> h2 ----
    agg_kernel<<<AGG_GRID, 256>>>(h1);
    gemm_kernel<<<GEMM_GRID, 256>>>(agg, h1, Wl2, Wr2, bl2, h2);

    // ---- layer 3: h2 -> out ----
    agg_kernel<<<AGG_GRID, 256>>>(h2);
    gemm_kernel<<<GEMM_GRID, 256>>>(agg, h2, Wl3, Wr3, bl3, out);
}

// round 4
// speedup vs baseline: 1.8198x; 1.8198x over previous
#include <cuda_runtime.h>
#include <cuda_bf16.h>
#include <cstdint>

#define N_NODES 50000
#define N_EDGES 600000
#define D 128
#define K2 256             // concat [agg|h] K dimension
#define NCHUNK 49          // ceil(50000/1024)

// ================= helpers ===================================================
__device__ __forceinline__ uint32_t smem_u32(const void* p) {
    uint32_t a;
    asm("{ .reg .u64 t; cvta.to.shared.u64 t, %1; cvt.u32.u64 %0, t; }" : "=r"(a) : "l"(p));
    return a;
}
#define SWZ128(off) ((off) ^ (((off) >> 3) & 0x70))

__device__ __forceinline__ void ldsm_x4(uint32_t* r, uint32_t addr) {
    asm volatile("ldmatrix.sync.aligned.m8n8.x4.shared.b16 {%0,%1,%2,%3}, [%4];"
        : "=r"(r[0]), "=r"(r[1]), "=r"(r[2]), "=r"(r[3]) : "r"(addr));
}
__device__ __forceinline__ void mma_bf16(float* d, const uint32_t* a, const uint32_t* b) {
    asm volatile(
        "mma.sync.aligned.m16n8k16.row.col.f32.bf16.bf16.f32 "
        "{%0,%1,%2,%3}, {%4,%5,%6,%7}, {%8,%9}, {%0,%1,%2,%3};"
        : "+f"(d[0]), "+f"(d[1]), "+f"(d[2]), "+f"(d[3])
        : "r"(a[0]), "r"(a[1]), "r"(a[2]), "r"(a[3]), "r"(b[0]), "r"(b[1]));
}
__device__ __forceinline__ void cp_async16(uint32_t dst, const void* src) {
    asm volatile("cp.async.cg.shared.global [%0], [%1], 16;" :: "r"(dst), "l"(src));
}
#define CP_COMMIT() asm volatile("cp.async.commit_group;" ::: "memory")
#define CP_WAIT0()  asm volatile("cp.async.wait_group 0;" ::: "memory")

__device__ __forceinline__ uint32_t pack2bf(float a, float b) {
    __nv_bfloat162 t = __floats2bfloat162_rn(a, b);
    return *(uint32_t*)&t;
}

// ================ scratch (static device globals) ============================
__device__ int   g_is64;
__device__ int   g_cnt[N_NODES];
__device__ int   g_rowptr[N_NODES + 1];
__device__ int   g_cursor[N_NODES];
__device__ int   g_bsum[64];
__device__ int   g_srcidx[N_EDGES];
__device__ float g_h1[(size_t)N_NODES * D];
__device__ float g_h2[(size_t)N_NODES * D];
__device__ __nv_bfloat16 g_Ahi[(size_t)N_NODES * K2];
__device__ __nv_bfloat16 g_Alo[(size_t)N_NODES * K2];
__device__ __nv_bfloat16 g_Bhi[3 * 128 * K2];
__device__ __nv_bfloat16 g_Blo[3 * 128 * K2];

__device__ __forceinline__ int edge_val(const void* ei, int idx) {
    if (g_is64) return (int)((const long long*)ei)[idx];
    return ((const int*)ei)[idx];
}

// ================ dtype detection + CSR build ================================
__global__ void detect_kernel(const int* __restrict__ ei32) {
    if (threadIdx.x == 0) {
        int is64 = 1;
        for (int i = 0; i < 64; i++)
            if (ei32[2 * i + 1] != 0) { is64 = 0; break; }
        g_is64 = is64;
    }
}
__global__ void zero_cnt_kernel() {
    int i = blockIdx.x * blockDim.x + threadIdx.x;
    if (i < N_NODES) g_cnt[i] = 0;
}
__global__ void count_kernel(const void* __restrict__ ei) {
    int e = blockIdx.x * blockDim.x + threadIdx.x;
    if (e < N_EDGES) atomicAdd(&g_cnt[edge_val(ei, N_EDGES + e)], 1);
}
__global__ void scan_partial_kernel() {
    __shared__ int s[1024];
    int i = blockIdx.x * 1024 + threadIdx.x;
    int v = (i < N_NODES) ? g_cnt[i] : 0;
    s[threadIdx.x] = v;
    __syncthreads();
    for (int off = 512; off > 0; off >>= 1) {
        if (threadIdx.x < off) s[threadIdx.x] += s[threadIdx.x + off];
        __syncthreads();
    }
    if (threadIdx.x == 0) g_bsum[blockIdx.x] = s[0];
}
__global__ void scan_bsums_kernel() {
    if (threadIdx.x == 0) {
        int acc = 0;
        for (int i = 0; i < NCHUNK; i++) { int v = g_bsum[i]; g_bsum[i] = acc; acc += v; }
    }
}
__global__ void scan_write_kernel() {
    __shared__ int s[1024];
    int i = blockIdx.x * 1024 + threadIdx.x;
    int v = (i < N_NODES) ? g_cnt[i] : 0;
    s[threadIdx.x] = v;
    __syncthreads();
    for (int off = 1; off < 1024; off <<= 1) {
        int t = (threadIdx.x >= off) ? s[threadIdx.x - off] : 0;
        __syncthreads();
        s[threadIdx.x] += t;
        __syncthreads();
    }
    if (i < N_NODES) {
        int excl = s[threadIdx.x] - v + g_bsum[blockIdx.x];
        g_rowptr[i] = excl;
        g_cursor[i] = excl;
        if (i == N_NODES - 1) g_rowptr[N_NODES] = excl + v;
    }
}
__global__ void fill_kernel(const void* __restrict__ ei) {
    int e = blockIdx.x * blockDim.x + threadIdx.x;
    if (e < N_EDGES) {
        int d = edge_val(ei, N_EDGES + e);
        int s = edge_val(ei, e);
        g_srcidx[atomicAdd(&g_cursor[d], 1)] = s;
    }
}

// ============== weight prep: Bcat[n,k] split to bf16 hi/lo ===================
__global__ void prep_weights_kernel(const float* __restrict__ Wl1, const float* __restrict__ Wr1,
                                    const float* __restrict__ Wl2, const float* __restrict__ Wr2,
                                    const float* __restrict__ Wl3, const float* __restrict__ Wr3) {
    int i = blockIdx.x * blockDim.x + threadIdx.x;   // 3*128*256
    if (i >= 3 * 128 * K2) return;
    int l = i / (128 * K2);
    int n = (i / K2) % 128;
    int k = i % K2;
    const float* Wl = (l == 0) ? Wl1 : (l == 1) ? Wl2 : Wl3;
    const float* Wr = (l == 0) ? Wr1 : (l == 1) ? Wr2 : Wr3;
    float v = (k < D) ? Wl[n * D + k] : Wr[n * D + (k - D)];
    __nv_bfloat16 hi = __float2bfloat16(v);
    float lo = v - __bfloat162float(hi);
    g_Bhi[i] = hi;
    g_Blo[i] = __float2bfloat16(lo);
}

// ============== x -> bf16 hi/lo into A cols [128..256) =======================
__global__ void xconv_kernel(const float* __restrict__ x) {
    int i = blockIdx.x * blockDim.x + threadIdx.x;   // one float4 each
    if (i >= N_NODES * 32) return;
    int row = i >> 5, c4 = i & 31;
    float4 v = *(const float4*)(x + (size_t)row * D + c4 * 4);
    __nv_bfloat16 h0 = __float2bfloat16(v.x), h1 = __float2bfloat16(v.y);
    __nv_bfloat16 h2 = __float2bfloat16(v.z), h3 = __float2bfloat16(v.w);
    uint2 hp, lp;
    hp.x = pack2bf(v.x, v.y); hp.y = pack2bf(v.z, v.w);
    lp.x = pack2bf(v.x - __bfloat162float(h0), v.y - __bfloat162float(h1));
    lp.y = pack2bf(v.z - __bfloat162float(h2), v.w - __bfloat162float(h3));
    size_t off = (size_t)row * K2 + D + c4 * 4;
    *(uint2*)(g_Ahi + off) = hp;
    *(uint2*)(g_Alo + off) = lp;
}

// ===== mean aggregation (warp/node) -> bf16 hi/lo into A cols [0..128) =======
__global__ void agg_kernel(const float* __restrict__ h) {
    int warp = (blockIdx.x * blockDim.x + threadIdx.x) >> 5;
    int lane = threadIdx.x & 31;
    if (warp >= N_NODES) return;
    int beg = g_rowptr[warp];
    int end = g_rowptr[warp + 1];
    float4 acc = make_float4(0.f, 0.f, 0.f, 0.f);
    for (int e = beg; e < end; e++) {
        int j = g_srcidx[e];
        float4 v = *(const float4*)(h + (size_t)j * D + lane * 4);
        acc.x += v.x; acc.y += v.y; acc.z += v.z; acc.w += v.w;
    }
    float inv = 1.0f / fmaxf((float)(end - beg), 1.0f);
    acc.x *= inv; acc.y *= inv; acc.z *= inv; acc.w *= inv;
    __nv_bfloat16 h0 = __float2bfloat16(acc.x), h1 = __float2bfloat16(acc.y);
    __nv_bfloat16 h2 = __float2bfloat16(acc.z), h3 = __float2bfloat16(acc.w);
    uint2 hp, lp;
    hp.x = pack2bf(acc.x, acc.y); hp.y = pack2bf(acc.z, acc.w);
    lp.x = pack2bf(acc.x - __bfloat162float(h0), acc.y - __bfloat162float(h1));
    lp.y = pack2bf(acc.z - __bfloat162float(h2), acc.w - __bfloat162float(h3));
    size_t off = (size_t)warp * K2 + lane * 4;
    *(uint2*)(g_Ahi + off) = hp;
    *(uint2*)(g_Alo + off) = lp;
}

// ================= bf16 mma.sync GEMM ========================================
// out[M=50000,128] = relu(Acat @ Bcat^T + bias), 3-term bf16 split:
//   seg0: A_hi.B_hi   seg1: A_hi.B_lo   seg2: A_lo.B_hi
// CTA: 128x128 tile, 8 warps (2m x 4n), warp tile 64x32.
// 12 K-chunks of 64 bf16, SW128 swizzled smem, cp.async double buffer.
#define SM_BIAS 0
#define SM_T0   1024
#define TILE_B  16384                  // 128 rows x 128 bytes
#define SM_TOTAL (1024 + 4 * TILE_B)   // 66560

__global__ __launch_bounds__(256)
void gemm_tc(const __nv_bfloat16* __restrict__ Ahi, const __nv_bfloat16* __restrict__ Alo,
             const __nv_bfloat16* __restrict__ Bhi, const __nv_bfloat16* __restrict__ Blo,
             const float* __restrict__ bias, float* __restrict__ out,
             __nv_bfloat16* __restrict__ nAhi, __nv_bfloat16* __restrict__ nAlo,
             int write_next) {
    extern __shared__ char smem[];
    const uint32_t sb = smem_u32(smem);
    const int tid = threadIdx.x;
    const int wid = tid >> 5, lane = tid & 31;
    const int wm = wid >> 2, wn = wid & 3;       // 2 x 4 warp grid
    const int m0 = blockIdx.x * 128;

    if (tid < 128) *(float*)(smem + SM_BIAS + tid * 4) = bias[tid];

    float acc[4][4][4];
#pragma unroll
    for (int i = 0; i < 4; i++)
#pragma unroll
        for (int j = 0; j < 4; j++)
#pragma unroll
            for (int q = 0; q < 4; q++) acc[i][j][q] = 0.f;

    // per-thread cp.async units: 4 for A, 4 for B (1024 16B units each tile)
    auto prefetch = [&](int c, int buf) {
        int seg = c >> 2, koff = (c & 3) * 64;
        const __nv_bfloat16* Ap = (seg < 2) ? Ahi : Alo;
        const __nv_bfloat16* Bp = (seg == 1) ? Blo : Bhi;
        uint32_t sA = sb + SM_T0 + buf * 2 * TILE_B;
        uint32_t sB = sA + TILE_B;
#pragma unroll
        for (int t = 0; t < 4; t++) {
            int u = tid + t * 256;               // 0..1023
            int row = u >> 3, f4 = u & 7;
            int gm = m0 + row;
            if (gm >= N_NODES) gm = N_NODES - 1; // rows discarded in epilogue
            cp_async16(sA + SWZ128(row * 128 + f4 * 16),
                       Ap + (size_t)gm * K2 + koff + f4 * 8);
            cp_async16(sB + SWZ128(row * 128 + f4 * 16),
                       Bp + (size_t)row * K2 + koff + f4 * 8);
        }
    };

    prefetch(0, 0);
    CP_COMMIT();

    for (int c = 0; c < 12; c++) {
        CP_WAIT0();
        __syncthreads();
        if (c + 1 < 12) { prefetch(c + 1, (c + 1) & 1); CP_COMMIT(); }

        uint32_t sA = sb + SM_T0 + (c & 1) * 2 * TILE_B;
        uint32_t sB = sA + TILE_B;
#pragma unroll
        for (int kk = 0; kk < 4; kk++) {
            uint32_t a[4][4], b[4][2];
#pragma unroll
            for (int mf = 0; mf < 4; mf++) {
                int row  = wm * 64 + mf * 16 + (lane & 15);
                int colb = kk * 32 + (lane >> 4) * 16;
                ldsm_x4(a[mf], sA + SWZ128(row * 128 + colb));
            }
#pragma unroll
            for (int nh = 0; nh < 2; nh++) {
                uint32_t r[4];
                int row  = wn * 32 + nh * 16 + (lane & 7) + ((lane >> 4) << 3);
                int colb = kk * 32 + ((lane >> 3) & 1) * 16;
                ldsm_x4(r, sB + SWZ128(row * 128 + colb));
                b[nh * 2][0] = r[0]; b[nh * 2][1] = r[1];
                b[nh * 2 + 1][0] = r[2]; b[nh * 2 + 1][1] = r[3];
            }
#pragma unroll
            for (int mf = 0; mf < 4; mf++)
#pragma unroll
                for (int nf = 0; nf < 4; nf++)
                    mma_bf16(acc[mf][nf], a[mf], b[nf]);
        }
        __syncthreads();   // all warps done with buf (c&1) before it is refilled
    }

    // epilogue: bias + relu + store fp32 (+ optional next-layer bf16 hi/lo)
    const int qr = lane >> 2;          // 0..7
    const int qc = (lane & 3) * 2;     // 0,2,4,6
#pragma unroll
    for (int mf = 0; mf < 4; mf++) {
        int r0 = m0 + wm * 64 + mf * 16 + qr;
        int r1 = r0 + 8;
#pragma unroll
        for (int nf = 0; nf < 4; nf++) {
            int col = wn * 32 + nf * 8 + qc;
            float b0 = *(const float*)(smem + SM_BIAS + col * 4);
            float b1 = *(const float*)(smem + SM_BIAS + (col + 1) * 4);
            float v00 = fmaxf(acc[mf][nf][0] + b0, 0.f);
            float v01 = fmaxf(acc[mf][nf][1] + b1, 0.f);
            float v10 = fmaxf(acc[mf][nf][2] + b0, 0.f);
            float v11 = fmaxf(acc[mf][nf][3] + b1, 0.f);
            if (r0 < N_NODES) {
                *(float2*)(out + (size_t)r0 * D + col) = make_float2(v00, v01);
                if (write_next) {
                    __nv_bfloat16 h0 = __float2bfloat16(v00), h1 = __float2bfloat16(v01);
                    size_t off = (size_t)r0 * K2 + D + col;
                    *(uint32_t*)(nAhi + off) = pack2bf(v00, v01);
                    *(uint32_t*)(nAlo + off) = pack2bf(v00 - __bfloat162float(h0),
                                                       v01 - __bfloat162float(h1));
                }
            }
            if (r1 < N_NODES) {
                *(float2*)(out + (size_t)r1 * D + col) = make_float2(v10, v11);
                if (write_next) {
                    __nv_bfloat16 h0 = __float2bfloat16(v10), h1 = __float2bfloat16(v11);
                    size_t off = (size_t)r1 * K2 + D + col;
                    *(uint32_t*)(nAhi + off) = pack2bf(v10, v11);
                    *(uint32_t*)(nAlo + off) = pack2bf(v10 - __bfloat162float(h0),
                                                       v11 - __bfloat162float(h1));
                }
            }
        }
    }
}

// ================= launch ====================================================
extern "C" void kernel_launch(void* const* d_in, const int* in_sizes, int n_in,
                              void* d_out, int out_size) {
    const float* x  = (const float*)d_in[0];
    const void*  ei = d_in[1];
    const float* Wl1 = (const float*)d_in[2];
    const float* bl1 = (const float*)d_in[3];
    const float* Wr1 = (const float*)d_in[4];
    const float* Wl2 = (const float*)d_in[5];
    const float* bl2 = (const float*)d_in[6];
    const float* Wr2 = (const float*)d_in[7];
    const float* Wl3 = (const float*)d_in[8];
    const float* bl3 = (const float*)d_in[9];
    const float* Wr3 = (const float*)d_in[10];
    float* out = (float*)d_out;

    float *h1, *h2;
    __nv_bfloat16 *Ahi, *Alo, *Bhi, *Blo;
    cudaGetSymbolAddress((void**)&h1,  g_h1);
    cudaGetSymbolAddress((void**)&h2,  g_h2);
    cudaGetSymbolAddress((void**)&Ahi, g_Ahi);
    cudaGetSymbolAddress((void**)&Alo, g_Alo);
    cudaGetSymbolAddress((void**)&Bhi, g_Bhi);
    cudaGetSymbolAddress((void**)&Blo, g_Blo);

    cudaFuncSetAttribute(gemm_tc, cudaFuncAttributeMaxDynamicSharedMemorySize, SM_TOTAL);

    // CSR build + weight/x prep
    detect_kernel<<<1, 32>>>((const int*)ei);
    zero_cnt_kernel<<<(N_NODES + 255) / 256, 256>>>();
    count_kernel<<<(N_EDGES + 255) / 256, 256>>>(ei);
    scan_partial_kernel<<<NCHUNK, 1024>>>();
    scan_bsums_kernel<<<1, 32>>>();
    scan_write_kernel<<<NCHUNK, 1024>>>();
    fill_kernel<<<(N_EDGES + 255) / 256, 256>>>(ei);
    prep_weights_kernel<<<(3 * 128 * K2 + 255) / 256, 256>>>(Wl1, Wr1, Wl2, Wr2, Wl3, Wr3);
    xconv_kernel<<<(N_NODES * 32 + 255) / 256, 256>>>(x);

    const int AGG_GRID  = (N_NODES * 32 + 255) / 256;
    const int GEMM_GRID = (N_NODES + 127) / 128;   // 391

    // layer 1: A = [agg(x) | x] -> h1 (+ next A cols 128..256)
    agg_kernel<<<AGG_GRID, 256>>>(x);
    gemm_tc<<<GEMM_GRID, 256, SM_TOTAL>>>(Ahi, Alo, Bhi, Blo, bl1, h1, Ahi, Alo, 1);

    // layer 2
    agg_kernel<<<AGG_GRID, 256>>>(h1);
    gemm_tc<<<GEMM_GRID, 256, SM_TOTAL>>>(Ahi, Alo, Bhi + 128 * K2, Blo + 128 * K2,
                                          bl2, h2, Ahi, Alo, 1);

    // layer 3 -> final output
    agg_kernel<<<AGG_GRID, 256>>>(h2);
    gemm_tc<<<GEMM_GRID, 256, SM_TOTAL>>>(Ahi, Alo, Bhi + 2 * 128 * K2, Blo + 2 * 128 * K2,
                                          bl3, out, (__nv_bfloat16*)nullptr,
                                          (__nv_bfloat16*)nullptr, 0);
}